// round 8
// baseline (speedup 1.0000x reference)
#include <cuda_runtime.h>
#include <math.h>

#define LEVEL 16
#define TPB 128
#define MAXG 4096

// Cross-CTA sync state. All counters are MONOTONIC across graph replays
// (never reset), so every launch is deterministic: each launch's arrivals
// occupy one epoch [e*G, (e+1)*G) of g_arrive and bump g_done exactly once.
__device__ double              g_partials[MAXG];
__device__ unsigned long long  g_arrive;   // zero-init at module load
__device__ unsigned long long  g_done;
__device__ double              g_vth;

// One ST-BIF neuron step (matches reference: neg overrides pos).
__device__ __forceinline__ float bif_step(float& v, float& T, float xt, float v_th) {
    v += xt;
    float s = 0.0f;
    if (v - v_th >= 0.0f && T - 15.0f < 0.0f) s = 1.0f;
    if (v < 0.0f && T > 0.0f)                 s = -1.0f;
    v -= v_th * s;
    T += s;
    return s;
}

__device__ __forceinline__ void scan_batch(const float4* r, float4* __restrict__ out,
                                           int j, int M4, float v_th) {
    float vx = 0.5f * v_th, vy = vx, vz = vx, vw = vx;
    float Tx = 0.f, Ty = 0.f, Tz = 0.f, Tw = 0.f;
#pragma unroll
    for (int t = 0; t < LEVEL; t++) {
        float4 o;
        o.x = bif_step(vx, Tx, r[t].x, v_th) * v_th;
        o.y = bif_step(vy, Ty, r[t].y, v_th) * v_th;
        o.z = bif_step(vz, Tz, r[t].z, v_th) * v_th;
        o.w = bif_step(vw, Tw, r[t].w, v_th) * v_th;
        __stcs(&out[(size_t)t * M4 + j], o);
    }
}

// ---------------------------------------------------------------------------
// Single-wave persistent fused kernel.
// Phase 1: reduction over all batches, LAST batch stashed in registers.
// Grid-wide epoch barrier (spin on monotonic g_done).
// Phase 2: scan stashed batch (0 re-read), then remaining batches in REVERSE
// phase-1 order so L2's LIFO residue is consumed while hottest.
// ---------------------------------------------------------------------------
__global__ void __launch_bounds__(TPB, 5) fused_kernel(const float4* __restrict__ x,
                                                       float4* __restrict__ out, int M4) {
    const int G = gridDim.x;
    const int P = G * TPB;                       // total threads
    const int p = blockIdx.x * TPB + threadIdx.x;
    const int B = (M4 + P - 1) / P;              // batches per thread

    // Epoch baseline: read BEFORE this CTA arrives (bump can only happen
    // after all CTAs, including this one, have arrived — so this read always
    // sees the pre-bump value).
    unsigned long long start = 0;
    if (threadIdx.x == 0) start = atomicAdd(&g_done, 0ULL);

    // ---- Phase 1: reduction; batches 0..B-2 discarded, B-1 stashed ----
    float acc = 0.0f;
    float4 r[LEVEL];

    for (int b = 0; b < B - 1; b++) {            // j < (B-1)*P <= M4, always valid
        int j = b * P + p;
        float sx = 0.f, sy = 0.f, sz = 0.f, sw = 0.f;
#pragma unroll
        for (int t = 0; t < LEVEL; t++) {
            float4 v = __ldcg(&x[(size_t)t * M4 + j]);
            sx += v.x; sy += v.y; sz += v.z; sw += v.w;
        }
        acc += fabsf(sx) + fabsf(sy) + fabsf(sz) + fabsf(sw);
    }

    const int jlast = (B - 1) * P + p;
    const bool valid = (jlast < M4);
    if (valid) {
        float sx = 0.f, sy = 0.f, sz = 0.f, sw = 0.f;
#pragma unroll
        for (int t = 0; t < LEVEL; t++) {
            r[t] = __ldcg(&x[(size_t)t * M4 + jlast]);
            sx += r[t].x; sy += r[t].y; sz += r[t].z; sw += r[t].w;
        }
        acc += fabsf(sx) + fabsf(sy) + fabsf(sz) + fabsf(sw);
    }

    // ---- CTA reduce to g_partials[blockIdx.x], then arrive ----
    int lane = threadIdx.x & 31, wid = threadIdx.x >> 5;
#pragma unroll
    for (int o = 16; o > 0; o >>= 1)
        acc += __shfl_down_sync(0xFFFFFFFFu, acc, o);

    __shared__ float wsum[TPB / 32];
    __shared__ bool  s_last;
    __shared__ float s_vth;
    if (lane == 0) wsum[wid] = acc;
    __syncthreads();
    if (threadIdx.x == 0) {
        float a = 0.f;
#pragma unroll
        for (int i = 0; i < TPB / 32; i++) a += wsum[i];
        g_partials[blockIdx.x] = (double)a;
        __threadfence();
        unsigned long long old = atomicAdd(&g_arrive, 1ULL);
        s_last = (((old + 1) % (unsigned long long)G) == 0ULL);
    }
    __syncthreads();

    // ---- last-arriving CTA computes v_th cooperatively ----
    if (s_last) {
        double d = 0.0;
        for (int i = threadIdx.x; i < G; i += TPB) d += g_partials[i];
#pragma unroll
        for (int o = 16; o > 0; o >>= 1)
            d += __shfl_down_sync(0xFFFFFFFFu, d, o);
        __shared__ double dsum[TPB / 32];
        if (lane == 0) dsum[wid] = d;
        __syncthreads();
        if (threadIdx.x == 0) {
            double tot = 0.0;
#pragma unroll
            for (int i = 0; i < TPB / 32; i++) tot += dsum[i];
            double mean = tot / (4.0 * (double)M4);
            g_vth = mean * 2.0 / sqrt(15.0);
            __threadfence();
            atomicAdd(&g_done, 1ULL);
        }
    }

    // ---- grid barrier: wait for this launch's epoch bump ----
    if (threadIdx.x == 0) {
        while (atomicAdd(&g_done, 0ULL) <= start) __nanosleep(128);
        __threadfence();
        s_vth = (float)(*(volatile double*)&g_vth);
    }
    __syncthreads();
    const float v_th = s_vth;

    // ---- Phase 2: scan. Stashed batch first (free), then reverse order ----
    if (valid) scan_batch(r, out, jlast, M4, v_th);

    for (int b = B - 2; b >= 0; b--) {
        int j = b * P + p;
#pragma unroll
        for (int t = 0; t < LEVEL; t++)
            r[t] = __ldcs(&x[(size_t)t * M4 + j]);
        scan_batch(r, out, j, M4, v_th);
    }
}

extern "C" void kernel_launch(void* const* d_in, const int* in_sizes, int n_in,
                              void* d_out, int out_size) {
    const float4* x = (const float4*)d_in[0];
    float4* out = (float4*)d_out;

    int n_total = in_sizes[0];         // 32*2048*1024
    int M4 = n_total / LEVEL / 4;      // 1,048,576 float4 columns

    // Single-wave grid: guaranteed co-residency so the spin-barrier is safe.
    int dev = 0;
    cudaGetDevice(&dev);
    int sms = 0;
    cudaDeviceGetAttribute(&sms, cudaDevAttrMultiProcessorCount, dev);
    int nb = 0;
    cudaOccupancyMaxActiveBlocksPerMultiprocessor(&nb, fused_kernel, TPB, 0);
    if (nb < 1) nb = 1;
    long long G = (long long)sms * nb;
    if (G > MAXG) G = MAXG;

    fused_kernel<<<(int)G, TPB>>>(x, out, M4);
}

// round 9
// speedup vs baseline: 1.0042x; 1.0042x over previous
#include <cuda_runtime.h>
#include <math.h>

#define LEVEL 16
#define TPB 128
#define MAXG 4096

// Cross-CTA sync: ONE monotonic arrival counter (never reset -> every graph
// replay is deterministic: launch e's arrivals occupy [e*G, (e+1)*G)).
__device__ double             g_partials[MAXG];
__device__ unsigned long long g_arrive;     // zero-init at module load

// One ST-BIF neuron step (matches reference: neg overrides pos).
__device__ __forceinline__ float bif_step(float& v, float& T, float xt, float v_th) {
    v += xt;
    float s = 0.0f;
    if (v - v_th >= 0.0f && T - 15.0f < 0.0f) s = 1.0f;
    if (v < 0.0f && T > 0.0f)                 s = -1.0f;
    v -= v_th * s;
    T += s;
    return s;
}

__device__ __forceinline__ void scan_batch(const float4* r, float4* __restrict__ out,
                                           int j, int M4, float v_th) {
    float vx = 0.5f * v_th, vy = vx, vz = vx, vw = vx;
    float Tx = 0.f, Ty = 0.f, Tz = 0.f, Tw = 0.f;
#pragma unroll
    for (int t = 0; t < LEVEL; t++) {
        float4 o;
        o.x = bif_step(vx, Tx, r[t].x, v_th) * v_th;
        o.y = bif_step(vy, Ty, r[t].y, v_th) * v_th;
        o.z = bif_step(vz, Tz, r[t].z, v_th) * v_th;
        o.w = bif_step(vw, Tw, r[t].w, v_th) * v_th;
        __stcs(&out[(size_t)t * M4 + j], o);
    }
}

// ---------------------------------------------------------------------------
// Single-wave persistent fused kernel, barrier hidden under memory:
//   Phase 1: forward reduction (no stash -> low regs across the barrier).
//   Arrive on g_arrive; immediately ISSUE the 16-load burst for batch B-1
//   (v_th-independent), THEN spin. Each CTA sums the partials itself.
//   Phase 2: batches B-1 .. 0 (LIFO vs phase 1 -> L2 residue hit hottest-first).
// ---------------------------------------------------------------------------
__global__ void __launch_bounds__(TPB) fused_kernel(const float4* __restrict__ x,
                                                    float4* __restrict__ out, int M4) {
    const int G = gridDim.x;
    const int P = G * TPB;                       // total threads
    const int p = blockIdx.x * TPB + threadIdx.x;
    const int B = (M4 + P - 1) / P;              // batches per thread
    const int lane = threadIdx.x & 31, wid = threadIdx.x >> 5;

    // ---- Phase 1: reduction over all batches (forward, __ldcg) ----
    float acc = 0.0f;
    for (int b = 0; b < B - 1; b++) {            // j < (B-1)*P <= M4 always
        int j = b * P + p;
        float sx = 0.f, sy = 0.f, sz = 0.f, sw = 0.f;
#pragma unroll
        for (int t = 0; t < LEVEL; t++) {
            float4 v = __ldcg(&x[(size_t)t * M4 + j]);
            sx += v.x; sy += v.y; sz += v.z; sw += v.w;
        }
        acc += fabsf(sx) + fabsf(sy) + fabsf(sz) + fabsf(sw);
    }
    {
        int j = (B - 1) * P + p;
        if (j < M4) {
            float sx = 0.f, sy = 0.f, sz = 0.f, sw = 0.f;
#pragma unroll
            for (int t = 0; t < LEVEL; t++) {
                float4 v = __ldcg(&x[(size_t)t * M4 + j]);
                sx += v.x; sy += v.y; sz += v.z; sw += v.w;
            }
            acc += fabsf(sx) + fabsf(sy) + fabsf(sz) + fabsf(sw);
        }
    }

    // ---- CTA reduce -> g_partials[blockIdx.x], then arrive ----
#pragma unroll
    for (int o = 16; o > 0; o >>= 1)
        acc += __shfl_down_sync(0xFFFFFFFFu, acc, o);

    __shared__ float wsum[TPB / 32];
    __shared__ unsigned long long s_target;
    __shared__ float s_vth;
    if (lane == 0) wsum[wid] = acc;
    __syncthreads();
    if (threadIdx.x == 0) {
        float a = 0.f;
#pragma unroll
        for (int i = 0; i < TPB / 32; i++) a += wsum[i];
        g_partials[blockIdx.x] = (double)a;
        __threadfence();
        unsigned long long old = atomicAdd(&g_arrive, 1ULL);
        s_target = (old / (unsigned long long)G + 1ULL) * (unsigned long long)G;
    }

    // ---- Issue batch B-1 load burst BEFORE the spin (hides barrier) ----
    const int jtop = (B - 1) * P + p;
    const bool vtop = (jtop < M4);
    float4 r[LEVEL];
    if (vtop) {
#pragma unroll
        for (int t = 0; t < LEVEL; t++)
            r[t] = __ldcs(&x[(size_t)t * M4 + jtop]);
    }

    __syncthreads();                              // publishes s_target

    // ---- Barrier + decentralized v_th (warp 0, loads overlap the spin) ----
    if (threadIdx.x < 32) {
        if (lane == 0) {
            while (atomicAdd(&g_arrive, 0ULL) < s_target) __nanosleep(64);
        }
        __syncwarp();
        __threadfence();
        double d = 0.0;
        for (int i = lane; i < G; i += 32)
            d += g_partials[i];
#pragma unroll
        for (int o = 16; o > 0; o >>= 1)
            d += __shfl_down_sync(0xFFFFFFFFu, d, o);
        if (lane == 0) {
            double mean = d / (4.0 * (double)M4);
            s_vth = (float)(mean * 2.0 / sqrt(15.0));
        }
    }
    __syncthreads();
    const float v_th = s_vth;

    // ---- Phase 2: scan batches B-1 .. 0 (LIFO for L2 hits) ----
    if (vtop) scan_batch(r, out, jtop, M4, v_th);

    for (int b = B - 2; b >= 0; b--) {
        int j = b * P + p;
#pragma unroll
        for (int t = 0; t < LEVEL; t++)
            r[t] = __ldcs(&x[(size_t)t * M4 + j]);
        scan_batch(r, out, j, M4, v_th);
    }
}

extern "C" void kernel_launch(void* const* d_in, const int* in_sizes, int n_in,
                              void* d_out, int out_size) {
    const float4* x = (const float4*)d_in[0];
    float4* out = (float4*)d_out;

    int n_total = in_sizes[0];         // 32*2048*1024
    int M4 = n_total / LEVEL / 4;      // 1,048,576 float4 columns

    // Single-wave grid: guaranteed co-residency so the spin-barrier is safe.
    int dev = 0;
    cudaGetDevice(&dev);
    int sms = 0;
    cudaDeviceGetAttribute(&sms, cudaDevAttrMultiProcessorCount, dev);
    int nb = 0;
    cudaOccupancyMaxActiveBlocksPerMultiprocessor(&nb, fused_kernel, TPB, 0);
    if (nb < 1) nb = 1;
    long long G = (long long)sms * nb;
    if (G > MAXG) G = MAXG;

    fused_kernel<<<(int)G, TPB>>>(x, out, M4);
}